// round 15
// baseline (speedup 1.0000x reference)
#include <cuda_runtime.h>
#include <cstddef>
#include <cstdint>

#define NROWS 32768
#define DDIM  64
#define RRULE 32
#define EPSF  1e-12f

#define WARPS_PER_BLOCK 8
#define ROWS_PER_WARP   4
#define THREADS (WARPS_PER_BLOCK * 32)
#define NBLOCKS (NROWS / (WARPS_PER_BLOCK * ROWS_PER_WARP))  // 1024
#define PSTRIDE 33

#define OFF_W   ((size_t)NROWS)
#define OFF_PHI ((size_t)NROWS + (size_t)NROWS * RRULE)
#define PHI_ROW (RRULE * (DDIM + 1))          // 2080 floats
#define PHI_VEC (PHI_ROW / 4)                 // 520 float4
#define ROW_BYTES (PHI_ROW * 4)               // 8320 B, 16B-multiple
#define WSPAD   35

// dynamic smem layout (bytes)
#define SM_C    0
#define SM_IS   (SM_C  + DDIM * PSTRIDE * 4)          // 8448
#define SM_TH   (SM_IS + DDIM * PSTRIDE * 4)          // 16896
#define SM_TB   (SM_TH + DDIM * PSTRIDE * 4)          // 25344
#define SM_X1   (SM_TB + 128)                          // 25472
#define SM_WS   (SM_X1 + WARPS_PER_BLOCK * ROWS_PER_WARP * 66 * 4)   // 33920
#define SM_ST   (SM_WS + WARPS_PER_BLOCK * ROWS_PER_WARP * WSPAD * 4) // 38400
#define SMEM_TOTAL (SM_ST + WARPS_PER_BLOCK * ROW_BYTES)              // 104960

__device__ __forceinline__ uint32_t smem_u32(const void* p) {
    uint32_t a;
    asm("{ .reg .u64 t; cvta.to.shared.u64 t, %1; cvt.u32.u64 %0, t; }"
        : "=r"(a) : "l"(p));
    return a;
}

__global__ __launch_bounds__(THREADS)
void tsk_kernel(const float* __restrict__ Xz,
                const float* __restrict__ C,
                const float* __restrict__ S,
                const float* __restrict__ Th,
                float* __restrict__ out)
{
    extern __shared__ unsigned char smem[];
    float* c_sh  = (float*)(smem + SM_C);
    float* is_sh = (float*)(smem + SM_IS);
    float* th_sh = (float*)(smem + SM_TH);
    float* tb_sh = (float*)(smem + SM_TB);
    float* x1_sh = (float*)(smem + SM_X1);   // [warp*4+q][66], [0]=1,[1..64]=x
    float* ws_sh = (float*)(smem + SM_WS);   // [warp*4+q][35]

    const int tid  = threadIdx.x;
    const int warp = tid >> 5;
    const int lane = tid & 31;

    // ---- params to shared, transposed [d][r] ----
    for (int i = tid; i < RRULE * DDIM; i += THREADS) {
        int r = i / DDIM, d = i % DDIM;
        c_sh [d * PSTRIDE + r] = C[i];
        is_sh[d * PSTRIDE + r] = 1.0f / (S[i] + EPSF);
    }
    for (int i = tid; i < RRULE * (DDIM + 1); i += THREADS) {
        int r = i / (DDIM + 1), k = i % (DDIM + 1);
        if (k == 0) tb_sh[r] = Th[i];
        else        th_sh[(k - 1) * PSTRIDE + r] = Th[i];
    }

    const int row0 = (blockIdx.x * WARPS_PER_BLOCK + warp) * ROWS_PER_WARP;
    float* x1w = x1_sh + (warp * ROWS_PER_WARP) * 66;
    float* wsw = ws_sh + (warp * ROWS_PER_WARP) * WSPAD;

    // ---- 4 rows of x into x1 (leading 1 per row) ----
    {
        const float* xg = Xz + (size_t)row0 * DDIM;
        #pragma unroll
        for (int i = 0; i < 8; i++) {
            const int idx = i * 32 + lane;
            x1w[(idx >> 6) * 66 + 1 + (idx & 63)] = xg[idx];
        }
        if (lane < ROWS_PER_WARP) x1w[lane * 66] = 1.0f;
        if (lane < ROWS_PER_WARP * 3)   // zero ws padding [32..34]
            wsw[(lane / 3) * WSPAD + RRULE + (lane % 3)] = 0.0f;
    }
    __syncthreads();

    // ---- membership + affine accumulators (lane = rule) ----
    float acc0 = 0.f, acc1 = 0.f, acc2 = 0.f, acc3 = 0.f;
    const float tb = tb_sh[lane];
    float t0 = tb, t1 = tb, t2 = tb, t3 = tb;

    #pragma unroll 8
    for (int d = 0; d < DDIM; d++) {
        const float c  = c_sh [d * PSTRIDE + lane];
        const float is = is_sh[d * PSTRIDE + lane];
        const float th = th_sh[d * PSTRIDE + lane];
        float x, z;
        x = x1w[0 * 66 + d + 1]; z = (x - c) * is; acc0 = fmaf(z, z, acc0); t0 = fmaf(th, x, t0);
        x = x1w[1 * 66 + d + 1]; z = (x - c) * is; acc1 = fmaf(z, z, acc1); t1 = fmaf(th, x, t1);
        x = x1w[2 * 66 + d + 1]; z = (x - c) * is; acc2 = fmaf(z, z, acc2); t2 = fmaf(th, x, t2);
        x = x1w[3 * 66 + d + 1]; z = (x - c) * is; acc3 = fmaf(z, z, acc3); t3 = fmaf(th, x, t3);
    }

    // ---- softmax + w/y outputs ----
    {
        const float accs[4] = {acc0, acc1, acc2, acc3};
        const float ts[4]   = {t0, t1, t2, t3};
        #pragma unroll
        for (int q = 0; q < ROWS_PER_WARP; q++) {
            float lw = -0.5f * accs[q];
            float mx = lw;
            #pragma unroll
            for (int o = 16; o > 0; o >>= 1)
                mx = fmaxf(mx, __shfl_xor_sync(0xFFFFFFFFu, mx, o));
            float e = __expf(lw - mx);
            float s = e;
            #pragma unroll
            for (int o = 16; o > 0; o >>= 1)
                s += __shfl_xor_sync(0xFFFFFFFFu, s, o);
            float w = e / (s + EPSF);
            wsw[q * WSPAD + lane] = w;
            out[OFF_W + (size_t)(row0 + q) * RRULE + lane] = w;
            float p = w * ts[q];
            #pragma unroll
            for (int o = 16; o > 0; o >>= 1)
                p += __shfl_xor_sync(0xFFFFFFFFu, p, o);
            if (lane == 0) out[row0 + q] = p;
        }
    }
    __syncwarp();

    // ---- Phi: per-row smem staging + TMA 1D bulk store ----
    float4* stage4 = (float4*)(smem + SM_ST + warp * ROW_BYTES);
    const uint32_t stage_sa = smem_u32(stage4);
    float* __restrict__ phi = out + OFF_PHI + (size_t)row0 * PHI_ROW;

    #pragma unroll 1
    for (int q = 0; q < ROWS_PER_WARP; q++) {
        if (q > 0) {       // buffer reusable once TMA has read it
            if (lane == 0)
                asm volatile("cp.async.bulk.wait_group.read 0;" ::: "memory");
            __syncwarp();
        }

        // sliding register window for this row: V[i] = x1_q[(k0+i) mod 65]
        const float* x1q = x1w + q * 66;
        const float* wsq = wsw + q * WSPAD;
        float V[4];
        int k0 = 4 * lane;
        int r0 = 0;
        if (k0 >= 65) { k0 -= 65; r0 = 1; }
        #pragma unroll
        for (int i = 0; i < 4; i++) {
            int k = k0 + i; if (k >= 65) k -= 65;
            V[i] = x1q[k];
        }

        // 16 full iterations -> STS.128 into stage
        #pragma unroll 1
        for (int j = 0; j < 16; j++) {
            const bool s0 = (k0 + 0 < 65), s1 = (k0 + 1 < 65),
                       s2 = (k0 + 2 < 65), s3 = (k0 + 3 < 65);
            const float wA = wsq[r0];
            const float wB = wsq[r0 + 1];
            float4 o4;
            o4.x = V[0] * (s0 ? wA : wB);
            o4.y = V[1] * (s1 ? wA : wB);
            o4.z = V[2] * (s2 ? wA : wB);
            o4.w = V[3] * (s3 ? wA : wB);
            stage4[j * 32 + lane] = o4;

            // slide window by -2 (mod 65)
            float a2 = __shfl_up_sync(0xFFFFFFFFu, V[2], 1);
            float a3 = __shfl_up_sync(0xFFFFFFFFu, V[3], 1);
            float u3 = __shfl_sync(0xFFFFFFFFu, V[3], 15);
            float u0 = __shfl_sync(0xFFFFFFFFu, V[0], 16);
            float n0 = (lane == 0) ? u3 : a2;
            float n1 = (lane == 0) ? u0 : a3;
            V[3] = V[1];
            V[2] = V[0];
            V[0] = n0;
            V[1] = n1;
            const int bump = (k0 >= 2) ? 2 : 1;
            const int kn   = (k0 >= 2) ? (k0 - 2) : (k0 + 63);
            r0 += bump;
            k0 = kn;
        }
        // peeled iteration: v = 512 + lane, live lanes 0..7
        if (lane < PHI_VEC - 512) {
            const bool s0 = (k0 + 0 < 65), s1 = (k0 + 1 < 65),
                       s2 = (k0 + 2 < 65), s3 = (k0 + 3 < 65);
            const float wA = wsq[r0];
            const float wB = wsq[r0 + 1];
            float4 o4;
            o4.x = V[0] * (s0 ? wA : wB);
            o4.y = V[1] * (s1 ? wA : wB);
            o4.z = V[2] * (s2 ? wA : wB);
            o4.w = V[3] * (s3 ? wA : wB);
            stage4[512 + lane] = o4;
        }

        __syncwarp();
        asm volatile("fence.proxy.async.shared::cta;" ::: "memory");
        __syncwarp();
        if (lane == 0) {
            asm volatile(
                "cp.async.bulk.global.shared::cta.bulk_group [%0], [%1], %2;"
                :: "l"(phi + (size_t)q * PHI_ROW), "r"(stage_sa), "r"(ROW_BYTES)
                : "memory");
            asm volatile("cp.async.bulk.commit_group;" ::: "memory");
        }
    }

    // drain before exit
    if (lane == 0)
        asm volatile("cp.async.bulk.wait_group 0;" ::: "memory");
}

extern "C" void kernel_launch(void* const* d_in, const int* in_sizes, int n_in,
                              void* d_out, int out_size)
{
    const float* Xz = (const float*)d_in[0];
    const float* C  = (const float*)d_in[1];
    const float* S  = (const float*)d_in[2];
    const float* Th = (const float*)d_in[3];
    float* out = (float*)d_out;
    (void)in_sizes; (void)n_in; (void)out_size;
    cudaFuncSetAttribute(tsk_kernel, cudaFuncAttributeMaxDynamicSharedMemorySize,
                         SMEM_TOTAL);
    tsk_kernel<<<NBLOCKS, THREADS, SMEM_TOTAL>>>(Xz, C, S, Th, out);
}